// round 4
// baseline (speedup 1.0000x reference)
#include <cuda_runtime.h>
#include <cuda_bf16.h>
#include <math.h>
#include <stdint.h>

#define BQ   16384
#define DIN  256
#define DHID 512
#define DOUT 256
#define NE   8
#define BKC  32

// ---------------- scratch (static device globals; no allocations) ----------
__device__ int   g_count[NE];
__device__ int   g_base[NE];
__device__ int   g_list[NE * BQ];                 // pair id (2t+k) per (expert, slot)
__device__ float g_pw[2 * BQ];
__device__ __align__(16) __nv_bfloat16 g_x_hi[(size_t)BQ * DIN];
__device__ __align__(16) __nv_bfloat16 g_x_lo[(size_t)BQ * DIN];
__device__ __align__(16) __nv_bfloat16 g_W1_hi[NE * DIN * DHID];   // [e][k][n]
__device__ __align__(16) __nv_bfloat16 g_W1_lo[NE * DIN * DHID];
__device__ __align__(16) __nv_bfloat16 g_W2_hi[NE * DHID * DOUT];  // [e][k][n]
__device__ __align__(16) __nv_bfloat16 g_W2_lo[NE * DHID * DOUT];
__device__ __align__(16) __nv_bfloat16 g_H_hi[(size_t)2 * BQ * DHID];  // slot space
__device__ __align__(16) __nv_bfloat16 g_H_lo[(size_t)2 * BQ * DHID];
__device__ __align__(16) float g_O2[(size_t)2 * BQ * DOUT];            // pair space

// ---------------- helpers ----------------------------------------------------
__device__ __forceinline__ uint32_t smem_u32(const void* p) {
    return (uint32_t)__cvta_generic_to_shared(p);
}
__device__ __forceinline__ void ldmx4(uint32_t* r, uint32_t a) {
    asm volatile("ldmatrix.sync.aligned.m8n8.x4.shared.b16 {%0,%1,%2,%3}, [%4];"
                 : "=r"(r[0]), "=r"(r[1]), "=r"(r[2]), "=r"(r[3]) : "r"(a));
}
__device__ __forceinline__ void ldmx4t(uint32_t* r, uint32_t a) {
    asm volatile("ldmatrix.sync.aligned.m8n8.x4.trans.shared.b16 {%0,%1,%2,%3}, [%4];"
                 : "=r"(r[0]), "=r"(r[1]), "=r"(r[2]), "=r"(r[3]) : "r"(a));
}
__device__ __forceinline__ void mma16816(float* d, const uint32_t* a, const uint32_t* b) {
    asm volatile("mma.sync.aligned.m16n8k16.row.col.f32.bf16.bf16.f32 "
                 "{%0,%1,%2,%3}, {%4,%5,%6,%7}, {%8,%9}, {%0,%1,%2,%3};"
                 : "+f"(d[0]), "+f"(d[1]), "+f"(d[2]), "+f"(d[3])
                 : "r"(a[0]), "r"(a[1]), "r"(a[2]), "r"(a[3]), "r"(b[0]), "r"(b[1]));
}
__device__ __forceinline__ void cpa16(uint32_t dst, const void* src) {
    asm volatile("cp.async.cg.shared.global [%0], [%1], 16;" :: "r"(dst), "l"(src));
}
__device__ __forceinline__ void cp_commit() { asm volatile("cp.async.commit_group;"); }
__device__ __forceinline__ void cp_wait1() { asm volatile("cp.async.wait_group 1;"); }
__device__ __forceinline__ void cp_wait0() { asm volatile("cp.async.wait_group 0;"); }

__device__ __forceinline__ void split_pack(float f0, float f1, uint32_t& hi, uint32_t& lo) {
    __nv_bfloat16 h0 = __float2bfloat16_rn(f0);
    __nv_bfloat16 h1 = __float2bfloat16_rn(f1);
    __nv_bfloat16 l0 = __float2bfloat16_rn(f0 - __bfloat162float(h0));
    __nv_bfloat16 l1 = __float2bfloat16_rn(f1 - __bfloat162float(h1));
    __nv_bfloat162 H = __halves2bfloat162(h0, h1);
    __nv_bfloat162 L = __halves2bfloat162(l0, l1);
    hi = *reinterpret_cast<uint32_t*>(&H);
    lo = *reinterpret_cast<uint32_t*>(&L);
}

// SMEM layout (bytes). 3 stages. A: 128 rows x 80B. B: 32 rows x 272B.
#define A_PLANE 10240
#define A_STAGE 20480
#define B_PLANE 8704
#define B_STAGE 17408
#define SMO_A   1024
#define SMO_B   (1024 + 3 * A_STAGE)
#define SM_SZ   (SMO_B + 3 * B_STAGE)   // 114688

// ---------------- small kernels ---------------------------------------------
__global__ void zero_counts_kernel() {
    if (threadIdx.x < NE) g_count[threadIdx.x] = 0;
}
__global__ void prefix_kernel() {
    if (threadIdx.x == 0) {
        int s = 0;
        for (int e = 0; e < NE; e++) { g_base[e] = s; s += g_count[e]; }
    }
}

__global__ void gate_kernel(const float* __restrict__ x,
                            const float* __restrict__ Wg) {
    __shared__ float sWgT[NE * DIN];
    for (int i = threadIdx.x; i < NE * DIN; i += blockDim.x) {
        int e = i / DIN, d = i % DIN;
        sWgT[i] = Wg[d * NE + e];
    }
    __syncthreads();
    int gwarp = (blockIdx.x * blockDim.x + threadIdx.x) >> 5;
    int lane = threadIdx.x & 31;
    if (gwarp >= BQ) return;
    const float* xr = x + (size_t)gwarp * DIN;
    float acc[NE];
#pragma unroll
    for (int e = 0; e < NE; e++) acc[e] = 0.f;
#pragma unroll
    for (int it = 0; it < 2; it++) {
        int d = it * 128 + lane * 4;
        float4 xv = *(const float4*)(xr + d);
#pragma unroll
        for (int e = 0; e < NE; e++) {
            acc[e] += xv.x * sWgT[e * DIN + d]
                    + xv.y * sWgT[e * DIN + d + 1]
                    + xv.z * sWgT[e * DIN + d + 2]
                    + xv.w * sWgT[e * DIN + d + 3];
        }
    }
#pragma unroll
    for (int e = 0; e < NE; e++)
#pragma unroll
        for (int o = 16; o > 0; o >>= 1)
            acc[e] += __shfl_xor_sync(0xffffffffu, acc[e], o);
    if (lane == 0) {
        int e0 = 0; float v0 = acc[0];
#pragma unroll
        for (int e = 1; e < NE; e++) if (acc[e] > v0) { v0 = acc[e]; e0 = e; }
        int e1 = (e0 == 0) ? 1 : 0; float v1 = acc[e1];
#pragma unroll
        for (int e = 0; e < NE; e++)
            if (e != e0 && acc[e] > v1) { v1 = acc[e]; e1 = e; }
        float x1 = expf(v1 - v0);
        float w0 = 1.0f / (1.0f + x1);
        int t = gwarp;
        int s0 = atomicAdd(&g_count[e0], 1);
        g_list[e0 * BQ + s0] = 2 * t;
        g_pw[2 * t] = w0;
        int s1 = atomicAdd(&g_count[e1], 1);
        g_list[e1 * BQ + s1] = 2 * t + 1;
        g_pw[2 * t + 1] = 1.0f - w0;
    }
}

// fused fp32 -> bf16 hi/lo split for x, W1, W2 (8 elems per thread)
__global__ void split_all_kernel(const float* __restrict__ x,
                                 const float* __restrict__ W1,
                                 const float* __restrict__ W2) {
    const int NX  = BQ * DIN / 8;           // 524288
    const int NW1 = NE * DIN * DHID / 8;    // 131072
    const int NW2 = NE * DHID * DOUT / 8;   // 131072
    int i = blockIdx.x * blockDim.x + threadIdx.x;
    const float* src;
    __nv_bfloat16 *hi, *lo;
    size_t off;
    if (i < NX) {
        src = x; hi = g_x_hi; lo = g_x_lo; off = (size_t)i * 8;
    } else if (i < NX + NW1) {
        src = W1; hi = g_W1_hi; lo = g_W1_lo; off = (size_t)(i - NX) * 8;
    } else if (i < NX + NW1 + NW2) {
        src = W2; hi = g_W2_hi; lo = g_W2_lo; off = (size_t)(i - NX - NW1) * 8;
    } else return;
    float4 a = *(const float4*)(src + off);
    float4 b = *(const float4*)(src + off + 4);
    uint4 H, L;
    split_pack(a.x, a.y, H.x, L.x);
    split_pack(a.z, a.w, H.y, L.y);
    split_pack(b.x, b.y, H.z, L.z);
    split_pack(b.z, b.w, H.w, L.w);
    *(uint4*)(hi + off) = H;
    *(uint4*)(lo + off) = L;
}

// ---------------- GEMM1: H = relu(Xg @ W1[e] + b1[e]) ------------------------
__global__ void __launch_bounds__(256)
gemm1_kernel(const float* __restrict__ b1) {
    const int e = blockIdx.z;
    const int cnt = g_count[e];
    const int m0 = blockIdx.x * 128;
    if (m0 >= cnt) return;
    const int n0 = blockIdx.y * 128;

    extern __shared__ char smem[];
    uint32_t sbase = smem_u32(smem);
    int* tok = (int*)smem;
    const int tid = threadIdx.x;
    const int lane = tid & 31;
    const int wid = tid >> 5;
    const int wm = wid >> 1, wn = wid & 1;

    for (int r = tid; r < 128; r += 256) {
        int rr = m0 + r; if (rr >= cnt) rr = cnt - 1;
        tok[r] = g_list[e * BQ + rr] >> 1;
    }
    __syncthreads();

    auto issue = [&](int c, int s) {
        const int k0 = c * BKC;
        uint32_t abase = sbase + SMO_A + s * A_STAGE;
        uint32_t bbase = sbase + SMO_B + s * B_STAGE;
#pragma unroll
        for (int i = 0; i < 4; i++) {
            int idx = tid + i * 256;
            int plane = idx >> 9, rem = idx & 511;
            int row = rem >> 2, seg = rem & 3;
            const __nv_bfloat16* src =
                (plane ? g_x_lo : g_x_hi) + (size_t)tok[row] * DIN + k0 + seg * 8;
            cpa16(abase + plane * A_PLANE + row * 80 + seg * 16, src);
        }
#pragma unroll
        for (int i = 0; i < 4; i++) {
            int idx = tid + i * 256;
            int plane = idx >> 9, rem = idx & 511;
            int row = rem >> 4, seg = rem & 15;
            const __nv_bfloat16* src =
                (plane ? g_W1_lo : g_W1_hi) + ((size_t)e * DIN + k0 + row) * DHID + n0 + seg * 8;
            cpa16(bbase + plane * B_PLANE + row * 272 + seg * 16, src);
        }
        cp_commit();
    };

    float acc[2][8][4];
#pragma unroll
    for (int a = 0; a < 2; a++)
#pragma unroll
        for (int b = 0; b < 8; b++)
#pragma unroll
            for (int q = 0; q < 4; q++) acc[a][b][q] = 0.f;

    issue(0, 0);
    issue(1, 1);

    const int NC = DIN / BKC;   // 8
#pragma unroll 1
    for (int c = 0; c < NC; c++) {
        if (c == NC - 1) cp_wait0(); else cp_wait1();
        __syncthreads();
        if (c + 2 < NC) issue(c + 2, (c + 2) % 3);
        int s = c % 3;
        uint32_t abase = sbase + SMO_A + s * A_STAGE;
        uint32_t bbase = sbase + SMO_B + s * B_STAGE;
#pragma unroll
        for (int ks = 0; ks < 2; ks++) {
            uint32_t ah[2][4], al[2][4];
#pragma unroll
            for (int mi = 0; mi < 2; mi++) {
                uint32_t r = wm * 32 + mi * 16 + (lane & 15);
                uint32_t co = ks * 32 + ((lane >> 4) << 4);
                ldmx4(ah[mi], abase + r * 80 + co);
                ldmx4(al[mi], abase + A_PLANE + r * 80 + co);
            }
#pragma unroll
            for (int np = 0; np < 4; np++) {
                uint32_t kr = ks * 16 + ((lane >> 3) & 1) * 8 + (lane & 7);
                uint32_t nc = (wn * 64 + np * 16 + ((lane >> 4) << 3)) * 2;
                uint32_t bh[4], bl[4];
                ldmx4t(bh, bbase + kr * 272 + nc);
                ldmx4t(bl, bbase + B_PLANE + kr * 272 + nc);
#pragma unroll
                for (int mi = 0; mi < 2; mi++) {
                    mma16816(acc[mi][2 * np],     ah[mi], bh);
                    mma16816(acc[mi][2 * np],     ah[mi], bl);
                    mma16816(acc[mi][2 * np],     al[mi], bh);
                    mma16816(acc[mi][2 * np + 1], ah[mi], bh + 2);
                    mma16816(acc[mi][2 * np + 1], ah[mi], bl + 2);
                    mma16816(acc[mi][2 * np + 1], al[mi], bh + 2);
                }
            }
        }
    }

    // epilogue: bias + relu + split -> H planes (slot space)
    const int slot0 = g_base[e] + m0;
    float2 bn[8];
#pragma unroll
    for (int ni = 0; ni < 8; ni++) {
        int gc = n0 + wn * 64 + ni * 8 + 2 * (lane & 3);
        bn[ni].x = __ldg(b1 + e * DHID + gc);
        bn[ni].y = __ldg(b1 + e * DHID + gc + 1);
    }
#pragma unroll
    for (int mi = 0; mi < 2; mi++) {
#pragma unroll
        for (int h = 0; h < 2; h++) {
            int rl = wm * 32 + mi * 16 + h * 8 + (lane >> 2);
            if (m0 + rl >= cnt) continue;
            size_t rowo = (size_t)(slot0 + rl) * DHID;
#pragma unroll
            for (int ni = 0; ni < 8; ni++) {
                int gc = n0 + wn * 64 + ni * 8 + 2 * (lane & 3);
                float f0 = fmaxf(acc[mi][ni][2 * h]     + bn[ni].x, 0.f);
                float f1 = fmaxf(acc[mi][ni][2 * h + 1] + bn[ni].y, 0.f);
                uint32_t hw, lw;
                split_pack(f0, f1, hw, lw);
                *(uint32_t*)(g_H_hi + rowo + gc) = hw;
                *(uint32_t*)(g_H_lo + rowo + gc) = lw;
            }
        }
    }
}

// ---------------- GEMM2: O2 = Hg @ W2[e] + b2[e] ------------------------------
__global__ void __launch_bounds__(256)
gemm2_kernel(const float* __restrict__ b2) {
    const int e = blockIdx.z;
    const int cnt = g_count[e];
    const int m0 = blockIdx.x * 128;
    if (m0 >= cnt) return;
    const int n0 = blockIdx.y * 128;
    const int hbase = g_base[e];

    extern __shared__ char smem[];
    uint32_t sbase = smem_u32(smem);
    const int tid = threadIdx.x;
    const int lane = tid & 31;
    const int wid = tid >> 5;
    const int wm = wid >> 1, wn = wid & 1;

    auto issue = [&](int c, int s) {
        const int k0 = c * BKC;
        uint32_t abase = sbase + SMO_A + s * A_STAGE;
        uint32_t bbase = sbase + SMO_B + s * B_STAGE;
#pragma unroll
        for (int i = 0; i < 4; i++) {
            int idx = tid + i * 256;
            int plane = idx >> 9, rem = idx & 511;
            int row = rem >> 2, seg = rem & 3;
            int rg = m0 + row; if (rg >= cnt) rg = cnt - 1;
            const __nv_bfloat16* src =
                (plane ? g_H_lo : g_H_hi) + (size_t)(hbase + rg) * DHID + k0 + seg * 8;
            cpa16(abase + plane * A_PLANE + row * 80 + seg * 16, src);
        }
#pragma unroll
        for (int i = 0; i < 4; i++) {
            int idx = tid + i * 256;
            int plane = idx >> 9, rem = idx & 511;
            int row = rem >> 4, seg = rem & 15;
            const __nv_bfloat16* src =
                (plane ? g_W2_lo : g_W2_hi) + ((size_t)e * DHID + k0 + row) * DOUT + n0 + seg * 8;
            cpa16(bbase + plane * B_PLANE + row * 272 + seg * 16, src);
        }
        cp_commit();
    };

    float acc[2][8][4];
#pragma unroll
    for (int a = 0; a < 2; a++)
#pragma unroll
        for (int b = 0; b < 8; b++)
#pragma unroll
            for (int q = 0; q < 4; q++) acc[a][b][q] = 0.f;

    issue(0, 0);
    issue(1, 1);

    const int NC = DHID / BKC;  // 16
#pragma unroll 1
    for (int c = 0; c < NC; c++) {
        if (c == NC - 1) cp_wait0(); else cp_wait1();
        __syncthreads();
        if (c + 2 < NC) issue(c + 2, (c + 2) % 3);
        int s = c % 3;
        uint32_t abase = sbase + SMO_A + s * A_STAGE;
        uint32_t bbase = sbase + SMO_B + s * B_STAGE;
#pragma unroll
        for (int ks = 0; ks < 2; ks++) {
            uint32_t ah[2][4], al[2][4];
#pragma unroll
            for (int mi = 0; mi < 2; mi++) {
                uint32_t r = wm * 32 + mi * 16 + (lane & 15);
                uint32_t co = ks * 32 + ((lane >> 4) << 4);
                ldmx4(ah[mi], abase + r * 80 + co);
                ldmx4(al[mi], abase + A_PLANE + r * 80 + co);
            }
#pragma unroll
            for (int np = 0; np < 4; np++) {
                uint32_t kr = ks * 16 + ((lane >> 3) & 1) * 8 + (lane & 7);
                uint32_t nc = (wn * 64 + np * 16 + ((lane >> 4) << 3)) * 2;
                uint32_t bh[4], bl[4];
                ldmx4t(bh, bbase + kr * 272 + nc);
                ldmx4t(bl, bbase + B_PLANE + kr * 272 + nc);
#pragma unroll
                for (int mi = 0; mi < 2; mi++) {
                    mma16816(acc[mi][2 * np],     ah[mi], bh);
                    mma16816(acc[mi][2 * np],     ah[mi], bl);
                    mma16816(acc[mi][2 * np],     al[mi], bh);
                    mma16816(acc[mi][2 * np + 1], ah[mi], bh + 2);
                    mma16816(acc[mi][2 * np + 1], ah[mi], bl + 2);
                    mma16816(acc[mi][2 * np + 1], al[mi], bh + 2);
                }
            }
        }
    }

    // epilogue: +bias, scatter fp32 rows to O2 by pair id
    float2 bn[8];
#pragma unroll
    for (int ni = 0; ni < 8; ni++) {
        int gc = n0 + wn * 64 + ni * 8 + 2 * (lane & 3);
        bn[ni].x = __ldg(b2 + e * DOUT + gc);
        bn[ni].y = __ldg(b2 + e * DOUT + gc + 1);
    }
#pragma unroll
    for (int mi = 0; mi < 2; mi++) {
#pragma unroll
        for (int h = 0; h < 2; h++) {
            int rl = wm * 32 + mi * 16 + h * 8 + (lane >> 2);
            if (m0 + rl >= cnt) continue;
            int pid = __ldg(&g_list[e * BQ + m0 + rl]);
            float* orow = g_O2 + (size_t)pid * DOUT;
#pragma unroll
            for (int ni = 0; ni < 8; ni++) {
                int gc = n0 + wn * 64 + ni * 8 + 2 * (lane & 3);
                float2 v;
                v.x = acc[mi][ni][2 * h]     + bn[ni].x;
                v.y = acc[mi][ni][2 * h + 1] + bn[ni].y;
                *(float2*)(orow + gc) = v;
            }
        }
    }
}

// ---------------- combine ----------------------------------------------------
__global__ void combine_kernel(float* __restrict__ out) {
    int idx = blockIdx.x * blockDim.x + threadIdx.x;
    int t = idx / (DOUT / 4);
    int o = (idx % (DOUT / 4)) * 4;
    float w0 = g_pw[2 * t];
    float w1 = g_pw[2 * t + 1];
    float4 a = *(const float4*)(g_O2 + (size_t)(2 * t) * DOUT + o);
    float4 b = *(const float4*)(g_O2 + (size_t)(2 * t + 1) * DOUT + o);
    float4 r;
    r.x = w0 * a.x + w1 * b.x;
    r.y = w0 * a.y + w1 * b.y;
    r.z = w0 * a.z + w1 * b.z;
    r.w = w0 * a.w + w1 * b.w;
    *(float4*)(out + (size_t)t * DOUT + o) = r;
}

// ---------------- launch -----------------------------------------------------
extern "C" void kernel_launch(void* const* d_in, const int* in_sizes, int n_in,
                              void* d_out, int out_size) {
    const float* x  = (const float*)d_in[0];
    const float* Wg = (const float*)d_in[1];
    const float* W1 = (const float*)d_in[2];
    const float* b1 = (const float*)d_in[3];
    const float* W2 = (const float*)d_in[4];
    const float* b2 = (const float*)d_in[5];
    float* out = (float*)d_out;

    cudaFuncSetAttribute(gemm1_kernel, cudaFuncAttributeMaxDynamicSharedMemorySize, SM_SZ);
    cudaFuncSetAttribute(gemm2_kernel, cudaFuncAttributeMaxDynamicSharedMemorySize, SM_SZ);

    const int NSPLIT = (BQ * DIN + NE * DIN * DHID + NE * DHID * DOUT) / 8;  // 786432

    // launch order chosen so gemm2 is the 6th launch (ncu -s 5 -c 1)
    zero_counts_kernel<<<1, 32>>>();
    split_all_kernel<<<NSPLIT / 256, 256>>>(x, W1, W2);
    gate_kernel<<<BQ / 8, 256>>>(x, Wg);
    prefix_kernel<<<1, 32>>>();
    gemm1_kernel<<<dim3(BQ / 128, DHID / 128, NE), 256, SM_SZ>>>(b1);
    gemm2_kernel<<<dim3(BQ / 128, DOUT / 128, NE), 256, SM_SZ>>>(b2);
    combine_kernel<<<(BQ * DOUT / 4) / 256, 256>>>(out);
}

// round 5
// speedup vs baseline: 1.1927x; 1.1927x over previous
#include <cuda_runtime.h>
#include <cuda_bf16.h>
#include <math.h>
#include <stdint.h>

#define BQ   16384
#define DIN  256
#define DHID 512
#define DOUT 256
#define NE   8
#define BKC  32

// ---------------- scratch (static device globals; no allocations) ----------
__device__ int   g_count[NE];
__device__ int   g_list[NE * BQ];                 // pair id (2t+k) per (expert, slot)
__device__ float g_pw[2 * BQ];
__device__ __align__(16) __nv_bfloat16 g_x_hi[(size_t)BQ * DIN];
__device__ __align__(16) __nv_bfloat16 g_x_lo[(size_t)BQ * DIN];
__device__ __align__(16) __nv_bfloat16 g_W1_hi[NE * DIN * DHID];   // [e][k][n]
__device__ __align__(16) __nv_bfloat16 g_W1_lo[NE * DIN * DHID];
__device__ __align__(16) __nv_bfloat16 g_W2_hi[NE * DHID * DOUT];  // [e][k][n]
__device__ __align__(16) __nv_bfloat16 g_W2_lo[NE * DHID * DOUT];
__device__ __align__(16) __nv_bfloat16 g_H_hi[(size_t)2 * BQ * DHID];  // slot space
__device__ __align__(16) __nv_bfloat16 g_H_lo[(size_t)2 * BQ * DHID];

// ---------------- helpers ----------------------------------------------------
__device__ __forceinline__ uint32_t smem_u32(const void* p) {
    return (uint32_t)__cvta_generic_to_shared(p);
}
__device__ __forceinline__ void ldmx4(uint32_t* r, uint32_t a) {
    asm volatile("ldmatrix.sync.aligned.m8n8.x4.shared.b16 {%0,%1,%2,%3}, [%4];"
                 : "=r"(r[0]), "=r"(r[1]), "=r"(r[2]), "=r"(r[3]) : "r"(a));
}
__device__ __forceinline__ void ldmx4t(uint32_t* r, uint32_t a) {
    asm volatile("ldmatrix.sync.aligned.m8n8.x4.trans.shared.b16 {%0,%1,%2,%3}, [%4];"
                 : "=r"(r[0]), "=r"(r[1]), "=r"(r[2]), "=r"(r[3]) : "r"(a));
}
__device__ __forceinline__ void mma16816(float* d, const uint32_t* a, const uint32_t* b) {
    asm volatile("mma.sync.aligned.m16n8k16.row.col.f32.bf16.bf16.f32 "
                 "{%0,%1,%2,%3}, {%4,%5,%6,%7}, {%8,%9}, {%0,%1,%2,%3};"
                 : "+f"(d[0]), "+f"(d[1]), "+f"(d[2]), "+f"(d[3])
                 : "r"(a[0]), "r"(a[1]), "r"(a[2]), "r"(a[3]), "r"(b[0]), "r"(b[1]));
}
__device__ __forceinline__ void cpa16(uint32_t dst, const void* src) {
    asm volatile("cp.async.cg.shared.global [%0], [%1], 16;" :: "r"(dst), "l"(src));
}
__device__ __forceinline__ void cp_commit() { asm volatile("cp.async.commit_group;"); }
__device__ __forceinline__ void cp_wait1() { asm volatile("cp.async.wait_group 1;"); }
__device__ __forceinline__ void cp_wait0() { asm volatile("cp.async.wait_group 0;"); }

__device__ __forceinline__ void split_pack(float f0, float f1, uint32_t& hi, uint32_t& lo) {
    __nv_bfloat16 h0 = __float2bfloat16_rn(f0);
    __nv_bfloat16 h1 = __float2bfloat16_rn(f1);
    __nv_bfloat16 l0 = __float2bfloat16_rn(f0 - __bfloat162float(h0));
    __nv_bfloat16 l1 = __float2bfloat16_rn(f1 - __bfloat162float(h1));
    __nv_bfloat162 H = __halves2bfloat162(h0, h1);
    __nv_bfloat162 L = __halves2bfloat162(l0, l1);
    hi = *reinterpret_cast<uint32_t*>(&H);
    lo = *reinterpret_cast<uint32_t*>(&L);
}

__device__ __forceinline__ int expert_base(int e) {
    int b = 0;
#pragma unroll
    for (int i = 0; i < NE; i++)
        if (i < e) b += g_count[i];
    return b;
}

// SMEM layout (bytes). 2 stages. A: 128 rows x 80B. B: 32 rows x 272B.
#define A_PLANE 10240
#define A_STAGE 20480
#define B_PLANE 8704
#define B_STAGE 17408
#define SMO_A   1024
#define SMO_B   (1024 + 2 * A_STAGE)
#define SM_SZ   (SMO_B + 2 * B_STAGE)   // 76800

// ---------------- small kernels ---------------------------------------------
__global__ void gate_kernel(const float* __restrict__ x,
                            const float* __restrict__ Wg) {
    __shared__ float sWgT[NE * DIN];
    for (int i = threadIdx.x; i < NE * DIN; i += blockDim.x) {
        int e = i / DIN, d = i % DIN;
        sWgT[i] = Wg[d * NE + e];
    }
    __syncthreads();
    int gwarp = (blockIdx.x * blockDim.x + threadIdx.x) >> 5;
    int lane = threadIdx.x & 31;
    if (gwarp >= BQ) return;
    const float* xr = x + (size_t)gwarp * DIN;
    float acc[NE];
#pragma unroll
    for (int e = 0; e < NE; e++) acc[e] = 0.f;
#pragma unroll
    for (int it = 0; it < 2; it++) {
        int d = it * 128 + lane * 4;
        float4 xv = *(const float4*)(xr + d);
#pragma unroll
        for (int e = 0; e < NE; e++) {
            acc[e] += xv.x * sWgT[e * DIN + d]
                    + xv.y * sWgT[e * DIN + d + 1]
                    + xv.z * sWgT[e * DIN + d + 2]
                    + xv.w * sWgT[e * DIN + d + 3];
        }
    }
#pragma unroll
    for (int e = 0; e < NE; e++)
#pragma unroll
        for (int o = 16; o > 0; o >>= 1)
            acc[e] += __shfl_xor_sync(0xffffffffu, acc[e], o);
    if (lane == 0) {
        int e0 = 0; float v0 = acc[0];
#pragma unroll
        for (int e = 1; e < NE; e++) if (acc[e] > v0) { v0 = acc[e]; e0 = e; }
        int e1 = (e0 == 0) ? 1 : 0; float v1 = acc[e1];
#pragma unroll
        for (int e = 0; e < NE; e++)
            if (e != e0 && acc[e] > v1) { v1 = acc[e]; e1 = e; }
        float x1 = expf(v1 - v0);
        float w0 = 1.0f / (1.0f + x1);
        int t = gwarp;
        int s0 = atomicAdd(&g_count[e0], 1);
        g_list[e0 * BQ + s0] = 2 * t;
        g_pw[2 * t] = w0;
        int s1 = atomicAdd(&g_count[e1], 1);
        g_list[e1 * BQ + s1] = 2 * t + 1;
        g_pw[2 * t + 1] = 1.0f - w0;
    }
}

// weights fp32 -> bf16 hi/lo split (8 elems per thread)
__global__ void split_w_kernel(const float* __restrict__ W1,
                               const float* __restrict__ W2) {
    const int NW1 = NE * DIN * DHID / 8;    // 131072
    const int NW2 = NE * DHID * DOUT / 8;   // 131072
    int i = blockIdx.x * blockDim.x + threadIdx.x;
    const float* src;
    __nv_bfloat16 *hi, *lo;
    size_t off;
    if (i < NW1) {
        src = W1; hi = g_W1_hi; lo = g_W1_lo; off = (size_t)i * 8;
    } else if (i < NW1 + NW2) {
        src = W2; hi = g_W2_hi; lo = g_W2_lo; off = (size_t)(i - NW1) * 8;
    } else return;
    float4 a = *(const float4*)(src + off);
    float4 b = *(const float4*)(src + off + 4);
    uint4 H, L;
    split_pack(a.x, a.y, H.x, L.x);
    split_pack(a.z, a.w, H.y, L.y);
    split_pack(b.x, b.y, H.z, L.z);
    split_pack(b.z, b.w, H.w, L.w);
    *(uint4*)(hi + off) = H;
    *(uint4*)(lo + off) = L;
}

// x fp32 -> bf16 hi/lo split; block 0 also zeros the expert counters
__global__ void split_x_kernel(const float* __restrict__ x) {
    if (blockIdx.x == 0 && threadIdx.x < NE) g_count[threadIdx.x] = 0;
    int i = blockIdx.x * blockDim.x + threadIdx.x;
    if (i >= BQ * DIN / 8) return;
    size_t off = (size_t)i * 8;
    float4 a = *(const float4*)(x + off);
    float4 b = *(const float4*)(x + off + 4);
    uint4 H, L;
    split_pack(a.x, a.y, H.x, L.x);
    split_pack(a.z, a.w, H.y, L.y);
    split_pack(b.x, b.y, H.z, L.z);
    split_pack(b.z, b.w, H.w, L.w);
    *(uint4*)(g_x_hi + off) = H;
    *(uint4*)(g_x_lo + off) = L;
}

__global__ void zero_out_kernel(float* __restrict__ out) {
    int i = blockIdx.x * blockDim.x + threadIdx.x;
    ((float4*)out)[i] = make_float4(0.f, 0.f, 0.f, 0.f);
}

// ---------------- GEMM1: H = relu(Xg @ W1[e] + b1[e]) ------------------------
__global__ void __launch_bounds__(256, 2)
gemm1_kernel(const float* __restrict__ b1) {
    const int e = blockIdx.z;
    const int cnt = g_count[e];
    const int m0 = blockIdx.x * 128;
    if (m0 >= cnt) return;
    const int n0 = blockIdx.y * 128;

    extern __shared__ char smem[];
    uint32_t sbase = smem_u32(smem);
    int* tok = (int*)smem;
    const int tid = threadIdx.x;
    const int lane = tid & 31;
    const int wid = tid >> 5;
    const int wm = wid >> 1, wn = wid & 1;

    for (int r = tid; r < 128; r += 256) {
        int rr = m0 + r; if (rr >= cnt) rr = cnt - 1;
        tok[r] = g_list[e * BQ + rr] >> 1;
    }
    __syncthreads();

    auto issue = [&](int c, int s) {
        const int k0 = c * BKC;
        uint32_t abase = sbase + SMO_A + s * A_STAGE;
        uint32_t bbase = sbase + SMO_B + s * B_STAGE;
#pragma unroll
        for (int i = 0; i < 4; i++) {
            int idx = tid + i * 256;
            int plane = idx >> 9, rem = idx & 511;
            int row = rem >> 2, seg = rem & 3;
            const __nv_bfloat16* src =
                (plane ? g_x_lo : g_x_hi) + (size_t)tok[row] * DIN + k0 + seg * 8;
            cpa16(abase + plane * A_PLANE + row * 80 + seg * 16, src);
        }
#pragma unroll
        for (int i = 0; i < 4; i++) {
            int idx = tid + i * 256;
            int plane = idx >> 9, rem = idx & 511;
            int row = rem >> 4, seg = rem & 15;
            const __nv_bfloat16* src =
                (plane ? g_W1_lo : g_W1_hi) + ((size_t)e * DIN + k0 + row) * DHID + n0 + seg * 8;
            cpa16(bbase + plane * B_PLANE + row * 272 + seg * 16, src);
        }
        cp_commit();
    };

    float acc[2][8][4];
#pragma unroll
    for (int a = 0; a < 2; a++)
#pragma unroll
        for (int b = 0; b < 8; b++)
#pragma unroll
            for (int q = 0; q < 4; q++) acc[a][b][q] = 0.f;

    issue(0, 0);
    issue(1, 1);

    const int NC = DIN / BKC;   // 8
#pragma unroll 1
    for (int c = 0; c < NC; c++) {
        if (c == NC - 1) cp_wait0(); else cp_wait1();
        __syncthreads();
        int s = c & 1;
        uint32_t abase = sbase + SMO_A + s * A_STAGE;
        uint32_t bbase = sbase + SMO_B + s * B_STAGE;
#pragma unroll
        for (int ks = 0; ks < 2; ks++) {
            uint32_t ah[2][4], al[2][4];
#pragma unroll
            for (int mi = 0; mi < 2; mi++) {
                uint32_t r = wm * 32 + mi * 16 + (lane & 15);
                uint32_t co = ks * 32 + ((lane >> 4) << 4);
                ldmx4(ah[mi], abase + r * 80 + co);
                ldmx4(al[mi], abase + A_PLANE + r * 80 + co);
            }
#pragma unroll
            for (int np = 0; np < 4; np++) {
                uint32_t kr = ks * 16 + ((lane >> 3) & 1) * 8 + (lane & 7);
                uint32_t nc = (wn * 64 + np * 16 + ((lane >> 4) << 3)) * 2;
                uint32_t bh[4], bl[4];
                ldmx4t(bh, bbase + kr * 272 + nc);
                ldmx4t(bl, bbase + B_PLANE + kr * 272 + nc);
#pragma unroll
                for (int mi = 0; mi < 2; mi++) {
                    mma16816(acc[mi][2 * np],     ah[mi], bh);
                    mma16816(acc[mi][2 * np],     ah[mi], bl);
                    mma16816(acc[mi][2 * np],     al[mi], bh);
                    mma16816(acc[mi][2 * np + 1], ah[mi], bh + 2);
                    mma16816(acc[mi][2 * np + 1], ah[mi], bl + 2);
                    mma16816(acc[mi][2 * np + 1], al[mi], bh + 2);
                }
            }
        }
        __syncthreads();
        if (c + 2 < NC) issue(c + 2, s);
    }

    // epilogue: bias + relu + split -> H planes (slot space)
    const int slot0 = expert_base(e) + m0;
    float2 bn[8];
#pragma unroll
    for (int ni = 0; ni < 8; ni++) {
        int gc = n0 + wn * 64 + ni * 8 + 2 * (lane & 3);
        bn[ni].x = __ldg(b1 + e * DHID + gc);
        bn[ni].y = __ldg(b1 + e * DHID + gc + 1);
    }
#pragma unroll
    for (int mi = 0; mi < 2; mi++) {
#pragma unroll
        for (int h = 0; h < 2; h++) {
            int rl = wm * 32 + mi * 16 + h * 8 + (lane >> 2);
            if (m0 + rl >= cnt) continue;
            size_t rowo = (size_t)(slot0 + rl) * DHID;
#pragma unroll
            for (int ni = 0; ni < 8; ni++) {
                int gc = n0 + wn * 64 + ni * 8 + 2 * (lane & 3);
                float f0 = fmaxf(acc[mi][ni][2 * h]     + bn[ni].x, 0.f);
                float f1 = fmaxf(acc[mi][ni][2 * h + 1] + bn[ni].y, 0.f);
                uint32_t hw, lw;
                split_pack(f0, f1, hw, lw);
                *(uint32_t*)(g_H_hi + rowo + gc) = hw;
                *(uint32_t*)(g_H_lo + rowo + gc) = lw;
            }
        }
    }
}

// ---------------- GEMM2 + fused combine: out[t] += w * (Hg @ W2[e] + b2[e]) --
__global__ void __launch_bounds__(256, 2)
gemm2_kernel(const float* __restrict__ b2, float* __restrict__ out) {
    const int e = blockIdx.z;
    const int cnt = g_count[e];
    const int m0 = blockIdx.x * 128;
    if (m0 >= cnt) return;
    const int n0 = blockIdx.y * 128;
    const int hbase = expert_base(e);

    extern __shared__ char smem[];
    uint32_t sbase = smem_u32(smem);
    const int tid = threadIdx.x;
    const int lane = tid & 31;
    const int wid = tid >> 5;
    const int wm = wid >> 1, wn = wid & 1;

    auto issue = [&](int c, int s) {
        const int k0 = c * BKC;
        uint32_t abase = sbase + SMO_A + s * A_STAGE;
        uint32_t bbase = sbase + SMO_B + s * B_STAGE;
#pragma unroll
        for (int i = 0; i < 4; i++) {
            int idx = tid + i * 256;
            int plane = idx >> 9, rem = idx & 511;
            int row = rem >> 2, seg = rem & 3;
            int rg = m0 + row; if (rg >= cnt) rg = cnt - 1;
            const __nv_bfloat16* src =
                (plane ? g_H_lo : g_H_hi) + (size_t)(hbase + rg) * DHID + k0 + seg * 8;
            cpa16(abase + plane * A_PLANE + row * 80 + seg * 16, src);
        }
#pragma unroll
        for (int i = 0; i < 4; i++) {
            int idx = tid + i * 256;
            int plane = idx >> 9, rem = idx & 511;
            int row = rem >> 4, seg = rem & 15;
            const __nv_bfloat16* src =
                (plane ? g_W2_lo : g_W2_hi) + ((size_t)e * DHID + k0 + row) * DOUT + n0 + seg * 8;
            cpa16(bbase + plane * B_PLANE + row * 272 + seg * 16, src);
        }
        cp_commit();
    };

    float acc[2][8][4];
#pragma unroll
    for (int a = 0; a < 2; a++)
#pragma unroll
        for (int b = 0; b < 8; b++)
#pragma unroll
            for (int q = 0; q < 4; q++) acc[a][b][q] = 0.f;

    issue(0, 0);
    issue(1, 1);

    const int NC = DHID / BKC;  // 16
#pragma unroll 1
    for (int c = 0; c < NC; c++) {
        if (c == NC - 1) cp_wait0(); else cp_wait1();
        __syncthreads();
        int s = c & 1;
        uint32_t abase = sbase + SMO_A + s * A_STAGE;
        uint32_t bbase = sbase + SMO_B + s * B_STAGE;
#pragma unroll
        for (int ks = 0; ks < 2; ks++) {
            uint32_t ah[2][4], al[2][4];
#pragma unroll
            for (int mi = 0; mi < 2; mi++) {
                uint32_t r = wm * 32 + mi * 16 + (lane & 15);
                uint32_t co = ks * 32 + ((lane >> 4) << 4);
                ldmx4(ah[mi], abase + r * 80 + co);
                ldmx4(al[mi], abase + A_PLANE + r * 80 + co);
            }
#pragma unroll
            for (int np = 0; np < 4; np++) {
                uint32_t kr = ks * 16 + ((lane >> 3) & 1) * 8 + (lane & 7);
                uint32_t nc = (wn * 64 + np * 16 + ((lane >> 4) << 3)) * 2;
                uint32_t bh[4], bl[4];
                ldmx4t(bh, bbase + kr * 272 + nc);
                ldmx4t(bl, bbase + B_PLANE + kr * 272 + nc);
#pragma unroll
                for (int mi = 0; mi < 2; mi++) {
                    mma16816(acc[mi][2 * np],     ah[mi], bh);
                    mma16816(acc[mi][2 * np],     ah[mi], bl);
                    mma16816(acc[mi][2 * np],     al[mi], bh);
                    mma16816(acc[mi][2 * np + 1], ah[mi], bh + 2);
                    mma16816(acc[mi][2 * np + 1], ah[mi], bl + 2);
                    mma16816(acc[mi][2 * np + 1], al[mi], bh + 2);
                }
            }
        }
        __syncthreads();
        if (c + 2 < NC) issue(c + 2, s);
    }

    // epilogue: +bias, scale by combine weight, accumulate into out[token]
    float2 bn[8];
#pragma unroll
    for (int ni = 0; ni < 8; ni++) {
        int gc = n0 + wn * 64 + ni * 8 + 2 * (lane & 3);
        bn[ni].x = __ldg(b2 + e * DOUT + gc);
        bn[ni].y = __ldg(b2 + e * DOUT + gc + 1);
    }
#pragma unroll
    for (int mi = 0; mi < 2; mi++) {
#pragma unroll
        for (int h = 0; h < 2; h++) {
            int rl = wm * 32 + mi * 16 + h * 8 + (lane >> 2);
            if (m0 + rl >= cnt) continue;
            int pid = __ldg(&g_list[e * BQ + m0 + rl]);
            float w = g_pw[pid];
            float* orow = out + (size_t)(pid >> 1) * DOUT;
#pragma unroll
            for (int ni = 0; ni < 8; ni++) {
                int gc = n0 + wn * 64 + ni * 8 + 2 * (lane & 3);
                atomicAdd(orow + gc,     w * (acc[mi][ni][2 * h]     + bn[ni].x));
                atomicAdd(orow + gc + 1, w * (acc[mi][ni][2 * h + 1] + bn[ni].y));
            }
        }
    }
}

// ---------------- launch -----------------------------------------------------
extern "C" void kernel_launch(void* const* d_in, const int* in_sizes, int n_in,
                              void* d_out, int out_size) {
    const float* x  = (const float*)d_in[0];
    const float* Wg = (const float*)d_in[1];
    const float* W1 = (const float*)d_in[2];
    const float* b1 = (const float*)d_in[3];
    const float* W2 = (const float*)d_in[4];
    const float* b2 = (const float*)d_in[5];
    float* out = (float*)d_out;

    cudaFuncSetAttribute(gemm1_kernel, cudaFuncAttributeMaxDynamicSharedMemorySize, SM_SZ);
    cudaFuncSetAttribute(gemm2_kernel, cudaFuncAttributeMaxDynamicSharedMemorySize, SM_SZ);

    const int NW = (NE * DIN * DHID + NE * DHID * DOUT) / 8;  // 262144

    // 6 launches; gemm2 is launch #6 (ncu -s 5 -c 1 profiles it)
    split_w_kernel<<<NW / 256, 256>>>(W1, W2);
    split_x_kernel<<<(BQ * DIN / 8 + 255) / 256, 256>>>(x);
    gate_kernel<<<BQ / 8, 256>>>(x, Wg);
    zero_out_kernel<<<(BQ * DOUT / 4) / 256, 256>>>(out);
    gemm1_kernel<<<dim3(BQ / 128, DHID / 128, NE), 256, SM_SZ>>>(b1);
    gemm2_kernel<<<dim3(BQ / 128, DOUT / 128, NE), 256, SM_SZ>>>(b2, out);
}